// round 1
// baseline (speedup 1.0000x reference)
#include <cuda_runtime.h>
#include <math.h>

// Problem constants (fixed shapes)
#define BDIM   32
#define CDIM   64
#define HDIM   64
#define WDIM   64
#define KCODES 512
#define HW     (HDIM*WDIM)          // 4096
#define NPTS   (BDIM*HW)            // 131072
#define NQ     (NPTS*CDIM)          // 8388608
// Output layout: [loss(1) | quantized(NQ) | perplexity(1) | indices(NPTS)]
#define QOFF   1
#define POFF   (1+NQ)               // 8388609
#define IOFF   (2+NQ)               // 8388610

#define SMEM_BYTES ((CDIM*KCODES + 2*KCODES)*4)   // E + e2 + hist = 135168 B

__device__ float g_loss;
__device__ int   g_counts[KCODES];

__global__ void vq_init() {
    int t = threadIdx.x;
    if (t < KCODES) g_counts[t] = 0;
    if (t == 0) g_loss = 0.0f;
}

__global__ void __launch_bounds__(512, 1)
vq_main(const float* __restrict__ x, const float* __restrict__ emb,
        float* __restrict__ out) {
    extern __shared__ float sm[];
    float* sE    = sm;                       // [CDIM][KCODES], row-major (k contiguous)
    float* se2   = sm + CDIM*KCODES;         // [KCODES]
    int*   shist = (int*)(se2 + KCODES);     // [KCODES]
    __shared__ float wsum[16];

    const int tid = threadIdx.x;

    // Load embeddings [64,512] row-major -> smem (same layout), float4 coalesced
    {
        const float4* e4  = (const float4*)emb;
        float4*       sE4 = (float4*)sE;
        #pragma unroll
        for (int i = 0; i < (CDIM*KCODES/4)/512; i++)
            sE4[tid + i*512] = e4[tid + i*512];
    }
    shist[tid] = 0;
    __syncthreads();

    // ||e_k||^2 per code (thread tid handles code tid; column reads conflict-free)
    {
        float s = 0.0f;
        #pragma unroll 8
        for (int c = 0; c < CDIM; c++) {
            float v = sE[c*KCODES + tid];
            s = fmaf(v, v, s);
        }
        se2[tid] = s;
    }
    __syncthreads();

    // One point per thread. Consecutive tid -> consecutive w -> coalesced.
    const int p  = blockIdx.x * 512 + tid;
    const int b  = p >> 12;         // / HW
    const int hw = p & (HW - 1);
    const float* xp = x + (size_t)b * CDIM * HW + hw;

    float z[CDIM];
    #pragma unroll
    for (int c = 0; c < CDIM; c++) z[c] = xp[c * HW];

    // Argmin over 512 codes: dist_k = ||e_k||^2 - 2 * z.e_k  (||z||^2 constant)
    // 8 codes per tile via 4 packed f32x2 FMA chains.
    float best = 3.4e38f;
    int   bi   = 0;
    for (int k0 = 0; k0 < KCODES; k0 += 8) {
        unsigned long long a0 = 0, a1 = 0, a2 = 0, a3 = 0;
        const unsigned long long* rp =
            ((const unsigned long long*)sE) + (k0 >> 1);
        #pragma unroll
        for (int c = 0; c < CDIM; c++) {
            unsigned long long zz;
            asm("mov.b64 %0, {%1, %1};" : "=l"(zz) : "r"(__float_as_uint(z[c])));
            unsigned long long e0 = rp[0], e1 = rp[1], e2v = rp[2], e3 = rp[3];
            asm("fma.rn.f32x2 %0, %1, %2, %0;" : "+l"(a0) : "l"(zz), "l"(e0));
            asm("fma.rn.f32x2 %0, %1, %2, %0;" : "+l"(a1) : "l"(zz), "l"(e1));
            asm("fma.rn.f32x2 %0, %1, %2, %0;" : "+l"(a2) : "l"(zz), "l"(e2v));
            asm("fma.rn.f32x2 %0, %1, %2, %0;" : "+l"(a3) : "l"(zz), "l"(e3));
            rp += KCODES/2;   // next c row: 512 floats = 256 u64
        }
        unsigned int u[8];
        asm("mov.b64 {%0, %1}, %2;" : "=r"(u[0]), "=r"(u[1]) : "l"(a0));
        asm("mov.b64 {%0, %1}, %2;" : "=r"(u[2]), "=r"(u[3]) : "l"(a1));
        asm("mov.b64 {%0, %1}, %2;" : "=r"(u[4]), "=r"(u[5]) : "l"(a2));
        asm("mov.b64 {%0, %1}, %2;" : "=r"(u[6]), "=r"(u[7]) : "l"(a3));
        #pragma unroll
        for (int j = 0; j < 8; j++) {
            float dist = fmaf(-2.0f, __uint_as_float(u[j]), se2[k0 + j]);
            if (dist < best) { best = dist; bi = k0 + j; }   // strict < => first argmin
        }
    }

    // Index output (as float)
    out[IOFF + p] = (float)bi;

    // Histogram (shared, then flushed below)
    atomicAdd(&shist[bi], 1);

    // Gather quantized vector, write [B,C,H,W]-coalesced, accumulate (q-z)^2
    float lsum = 0.0f;
    float* oq = out + QOFF + (size_t)b * CDIM * HW + hw;
    #pragma unroll
    for (int c = 0; c < CDIM; c++) {
        float q  = sE[c*KCODES + bi];
        float df = q - z[c];
        lsum = fmaf(df, df, lsum);
        oq[c * HW] = q;
    }

    // Block-reduce loss partial
    #pragma unroll
    for (int o = 16; o > 0; o >>= 1)
        lsum += __shfl_down_sync(0xffffffffu, lsum, o);
    if ((tid & 31) == 0) wsum[tid >> 5] = lsum;
    __syncthreads();   // also orders all shist atomics before the flush below
    if (tid < 16) {
        float v = wsum[tid];
        #pragma unroll
        for (int o = 8; o > 0; o >>= 1)
            v += __shfl_down_sync(0xffffu, v, o);
        if (tid == 0) atomicAdd(&g_loss, v);
    }

    // Flush histogram to global
    int h = shist[tid];
    if (h) atomicAdd(&g_counts[tid], h);
}

__global__ void vq_final(float* __restrict__ out) {
    __shared__ float ws[16];
    int t = threadIdx.x;  // 512
    float pr = (float)g_counts[t] * (1.0f / (float)NPTS);
    float v  = pr * logf(pr + 1e-10f);
    #pragma unroll
    for (int o = 16; o > 0; o >>= 1)
        v += __shfl_down_sync(0xffffffffu, v, o);
    if ((t & 31) == 0) ws[t >> 5] = v;
    __syncthreads();
    if (t < 16) {
        float s = ws[t];
        #pragma unroll
        for (int o = 8; o > 0; o >>= 1)
            s += __shfl_down_sync(0xffffu, s, o);
        if (t == 0) {
            // loss = q_latent + 0.25*e_latent, and both equal mean((q-z)^2)
            out[0]    = g_loss * (1.25f / (float)NQ);
            out[POFF] = expf(-s);
        }
    }
}

extern "C" void kernel_launch(void* const* d_in, const int* in_sizes, int n_in,
                              void* d_out, int out_size) {
    const float* x   = (const float*)d_in[0];
    const float* emb = (const float*)d_in[1];
    float* out = (float*)d_out;

    cudaFuncSetAttribute(vq_main, cudaFuncAttributeMaxDynamicSharedMemorySize,
                         SMEM_BYTES);

    vq_init<<<1, 512>>>();
    vq_main<<<NPTS/512, 512, SMEM_BYTES>>>(x, emb, out);
    vq_final<<<1, 512>>>(out);
}